// round 1
// baseline (speedup 1.0000x reference)
#include <cuda_runtime.h>
#include <math_constants.h>

// Problem shape (fixed by setup_inputs): key/value [B, T, H] fp32.
#define BB   8
#define TT   2048
#define HH   768
#define NC   16            // chunks per sequence
#define LL   (TT / NC)     // 128 steps per chunk

#define N_CHUNK_STATES (BB * NC * HH)   // 98304

// Scratch for per-chunk states (local sums in pass1, incoming carries after pass2).
__device__ float g_sa[N_CHUNK_STATES];
__device__ float g_sb[N_CHUNK_STATES];
__device__ float g_sp[N_CHUNK_STATES];

// ---------------------------------------------------------------------------
// Pass 1: each thread owns one (b, chunk, h); runs the stabilized recurrence
// from the empty state over its L timesteps. Produces local (a, b, p).
// ---------------------------------------------------------------------------
__global__ __launch_bounds__(256) void wkv_pass1(
    const float* __restrict__ key,
    const float* __restrict__ val,
    const float* __restrict__ time_decay)
{
    int tid = blockIdx.x * blockDim.x + threadIdx.x;
    if (tid >= N_CHUNK_STATES) return;
    int h  = tid % HH;
    int bc = tid / HH;
    int c  = bc % NC;
    int b  = bc / NC;

    float w = -expf(time_decay[h]);

    const float* kp = key + (size_t)(b * TT + c * LL) * HH + h;
    const float* vp = val + (size_t)(b * TT + c * LL) * HH + h;

    float a = 0.0f, bsum = 0.0f, p = -CUDART_INF_F;

#pragma unroll 4
    for (int t = 0; t < LL; ++t) {
        float kt = kp[(size_t)t * HH];
        float vt = vp[(size_t)t * HH];
        float pw = p + w;
        float p2 = fmaxf(pw, kt);
        float e1 = __expf(pw - p2);   // exp(-inf)=0 handles the empty start
        float e2 = __expf(kt - p2);
        a    = fmaf(e1, a,    e2 * vt);
        bsum = fmaf(e1, bsum, e2);
        p = p2;
    }
    g_sa[tid] = a;
    g_sb[tid] = bsum;
    g_sp[tid] = p;
}

// ---------------------------------------------------------------------------
// Pass 2: one thread per (b, h). Sequential stabilized scan over the NC chunk
// summaries; rewrites the arrays in place so entry c holds the INCOMING carry
// state for chunk c. Chunk operator: state' = decay(state, w*L) (+) local_c.
// ---------------------------------------------------------------------------
__global__ __launch_bounds__(256) void wkv_pass2(
    const float* __restrict__ time_decay)
{
    int tid = blockIdx.x * blockDim.x + threadIdx.x;   // = b*HH + h
    if (tid >= BB * HH) return;
    int h = tid % HH;
    int b = tid / HH;

    float w  = -expf(time_decay[h]);
    float wL = w * (float)LL;

    float a = 0.0f, bsum = 0.0f, p = -CUDART_INF_F;

#pragma unroll
    for (int c = 0; c < NC; ++c) {
        int idx = (b * NC + c) * HH + h;
        float la = g_sa[idx];
        float lb = g_sb[idx];
        float lp = g_sp[idx];
        // publish the incoming carry for chunk c
        g_sa[idx] = a;
        g_sb[idx] = bsum;
        g_sp[idx] = p;
        // state <- decay(state, w*L) merged with the local chunk sum
        float pd = p + wL;                 // -inf stays -inf
        float pm = fmaxf(pd, lp);          // lp is always finite
        float s1 = __expf(pd - pm);
        float s2 = __expf(lp - pm);
        a    = fmaf(a,    s1, la * s2);
        bsum = fmaf(bsum, s1, lb * s2);
        p = pm;
    }
}

// ---------------------------------------------------------------------------
// Pass 3: each thread owns one (b, chunk, h); starts from the incoming carry
// and replays the chunk, emitting the wkv output at every timestep.
// ---------------------------------------------------------------------------
__global__ __launch_bounds__(256) void wkv_pass3(
    const float* __restrict__ key,
    const float* __restrict__ val,
    const float* __restrict__ time_decay,
    const float* __restrict__ time_first,
    float* __restrict__ out)
{
    int tid = blockIdx.x * blockDim.x + threadIdx.x;
    if (tid >= N_CHUNK_STATES) return;
    int h  = tid % HH;
    int bc = tid / HH;
    int c  = bc % NC;
    int b  = bc / NC;

    float w = -expf(time_decay[h]);
    float u = time_first[h];

    float a    = g_sa[tid];
    float bsum = g_sb[tid];
    float p    = g_sp[tid];

    size_t base = (size_t)(b * TT + c * LL) * HH + h;
    const float* kp = key + base;
    const float* vp = val + base;
    float*       op = out + base;

#pragma unroll 4
    for (int t = 0; t < LL; ++t) {
        float kt = kp[(size_t)t * HH];
        float vt = vp[(size_t)t * HH];

        // output: wkv_t = (a*e^(p-m) + e^(u+k-m)*v) / (b*e^(p-m) + e^(u+k-m))
        float uk = u + kt;
        float me = fmaxf(p, uk);           // uk finite -> me finite
        float sc = __expf(p  - me);
        float wt = __expf(uk - me);
        float num = fmaf(a,    sc, wt * vt);
        float den = fmaf(bsum, sc, wt);    // den >= wt > 0
        op[(size_t)t * HH] = __fdividef(num, den);

        // state update with decay
        float pw = p + w;
        float p2 = fmaxf(pw, kt);
        float e1 = __expf(pw - p2);
        float e2 = __expf(kt - p2);
        a    = fmaf(e1, a,    e2 * vt);
        bsum = fmaf(e1, bsum, e2);
        p = p2;
    }
}

// ---------------------------------------------------------------------------
extern "C" void kernel_launch(void* const* d_in, const int* in_sizes, int n_in,
                              void* d_out, int out_size)
{
    const float* key = (const float*)d_in[0];
    const float* val = (const float*)d_in[1];
    const float* td  = (const float*)d_in[2];
    const float* tf  = (const float*)d_in[3];
    float* out = (float*)d_out;

    (void)in_sizes; (void)n_in; (void)out_size;

    const int blk = 256;
    const int g1 = (N_CHUNK_STATES + blk - 1) / blk;   // 384
    const int g2 = (BB * HH + blk - 1) / blk;          // 24

    wkv_pass1<<<g1, blk>>>(key, val, td);
    wkv_pass2<<<g2, blk>>>(td);
    wkv_pass3<<<g1, blk>>>(key, val, td, tf, out);
}